// round 15
// baseline (speedup 1.0000x reference)
#include <cuda_runtime.h>
#include <cstdint>

typedef unsigned long long ull;
#define FULL 0xFFFFFFFFu

constexpr int NUM_GROUP  = 512;
constexpr int GROUP_SIZE = 32;
constexpr int TPB        = 512;
constexpr int MAXB       = 64;
constexpr int NBKT       = 4096;

__device__ int g_prog[MAXB];

__global__ void init_prog() {
    if (threadIdx.x < MAXB) g_prog[threadIdx.x] = 0;
}

// ---- packed f32x2 helpers (sm_100+) ----
__device__ __forceinline__ ull pack2(float a, float b) {
    ull r; asm("mov.b64 %0,{%1,%2};" : "=l"(r) : "f"(a), "f"(b)); return r;
}
__device__ __forceinline__ void unpack2(ull v, float& a, float& b) {
    asm("mov.b64 {%0,%1},%2;" : "=f"(a), "=f"(b) : "l"(v));
}
__device__ __forceinline__ ull addx2(ull a, ull b) {
    ull r; asm("add.rn.f32x2 %0,%1,%2;" : "=l"(r) : "l"(a), "l"(b)); return r;
}
__device__ __forceinline__ ull mulx2(ull a, ull b) {
    ull r; asm("mul.rn.f32x2 %0,%1,%2;" : "=l"(r) : "l"(a), "l"(b)); return r;
}
__device__ __forceinline__ ull fma2_(ull a, ull b, ull c) {
    ull r; asm("fma.rn.f32x2 %0,%1,%2,%3;" : "=l"(r) : "l"(a), "l"(b), "l"(c)); return r;
}
__device__ __forceinline__ uint32_t redux_max_u32(uint32_t v) {
    uint32_t r; asm("redux.sync.max.u32 %0, %1, 0xffffffff;" : "=r"(r) : "r"(v)); return r;
}
__device__ __forceinline__ uint32_t redux_min_u32(uint32_t v) {
    uint32_t r; asm("redux.sync.min.u32 %0, %1, 0xffffffff;" : "=r"(r) : "r"(v)); return r;
}
__device__ __forceinline__ void st_release_gpu(int* p, int v) {
    asm volatile("st.release.gpu.global.s32 [%0], %1;" :: "l"(p), "r"(v) : "memory");
}
__device__ __forceinline__ int ld_acquire_gpu(const int* p) {
    int v; asm volatile("ld.acquire.gpu.global.s32 %0, [%1];" : "=r"(v) : "l"(p) : "memory");
    return v;
}
__device__ __forceinline__ float warp_min_f(float v) {
    #pragma unroll
    for (int o = 16; o > 0; o >>= 1) v = fminf(v, __shfl_xor_sync(FULL, v, o));
    return v;
}
__device__ __forceinline__ float warp_max_f(float v) {
    #pragma unroll
    for (int o = 16; o > 0; o >>= 1) v = fmaxf(v, __shfl_xor_sync(FULL, v, o));
    return v;
}

// composite 2-D sort key: (x-quartile << 10) | y-bucket  -> [0, 4096)
__device__ __forceinline__ int cell_key(float x, float y) {
    int xc = (x > -0.674f) + (x > 0.0f) + (x > 0.674f);
    int yb = (int)((y + 5.0f) * 102.4f);
    yb = max(0, min(1023, yb));
    return (xc << 10) | yb;
}

// ============================================================
// Fused kernel, TPB=512:
//   blocks [0, B)        : FPS — single barrier/iter, 2-D cell pruning
//   blocks [B, B + 32*B) : kNN (r10 streaming, proven), batch-major
// FPS smem: Bx[N] By[N] Bz[N] floats, Bid[N] int, hist[NBKT] int
// ============================================================
__global__ __launch_bounds__(TPB)
void fused_kernel(const float* __restrict__ xyz,
                  float* __restrict__ nb,
                  float* __restrict__ centers,
                  int N, int B) {
    extern __shared__ float s[];
    const int tid  = threadIdx.x;
    const int lane = tid & 31;
    const int warp = tid >> 5;

    __shared__ int partial[TPB];

    if (blockIdx.x < (unsigned)B) {
        // ==================== FPS ====================
        const int b = blockIdx.x;
        const float* X = xyz + (size_t)b * 3 * N;
        const float* Y = X + N;
        const float* Z = Y + N;
        float* cout = centers + (size_t)b * NUM_GROUP * 3;

        float* Bx = s;
        float* By = s + N;
        float* Bz = s + 2 * N;
        int*   Bid  = (int*)(s + 3 * N);
        int*   hist = (int*)(s + 4 * N);

        __shared__ uint32_t vbuf[2][32];   // per-warp value bits (lanes 16..31 stay 0)
        __shared__ uint32_t pbuf[2][32];   // per-warp packed (oid<<16 | pos)
        if (tid < 64) {
            vbuf[tid >> 5][tid & 31] = 0u;
            pbuf[tid >> 5][tid & 31] = 0xFFFFFFFFu;
        }

        // ---- counting sort by 2-D cell key ----
        #pragma unroll
        for (int k = 0; k < NBKT / TPB; k++) hist[tid + k * TPB] = 0;
        __syncthreads();
        for (int i = tid; i < N; i += TPB) {
            int bkt = cell_key(X[i], Y[i]);
            atomicAdd(&hist[bkt], 1);
        }
        __syncthreads();
        int loc[8], mysum = 0;
        #pragma unroll
        for (int k = 0; k < 8; k++) { loc[k] = hist[tid * 8 + k]; mysum += loc[k]; }
        partial[tid] = mysum;
        __syncthreads();
        for (int off = 1; off < TPB; off <<= 1) {
            int v = (tid >= off) ? partial[tid - off] : 0;
            __syncthreads();
            partial[tid] += v;
            __syncthreads();
        }
        {
            int run = partial[tid] - mysum;
            #pragma unroll
            for (int k = 0; k < 8; k++) { int c = loc[k]; hist[tid * 8 + k] = run; run += c; }
        }
        __syncthreads();
        for (int i = tid; i < N; i += TPB) {
            float x = X[i], y = Y[i];
            int bkt = cell_key(x, y);
            int pos = atomicAdd(&hist[bkt], 1);
            Bx[pos]  = x;
            By[pos]  = y;
            Bz[pos]  = Z[i];
            Bid[pos] = i;
        }
        __syncthreads();

        // ---- 16 contiguous cell-sorted points per thread ----
        ull  pxp[8], pyp[8], pzp[8];
        uint32_t oidpos[16];               // (original_id << 16) | sorted_pos
        float md[16];
        const int base = 512 * warp + 16 * lane;
        float mnx = 1e30f, mxx = -1e30f, mny = 1e30f, mxy = -1e30f;
        #pragma unroll
        for (int i = 0; i < 8; i++) {
            int n0 = base + 2 * i;
            float x0 = Bx[n0], x1 = Bx[n0 + 1];
            float y0 = By[n0], y1 = By[n0 + 1];
            pxp[i] = pack2(x0, x1);
            pyp[i] = pack2(y0, y1);
            pzp[i] = pack2(Bz[n0], Bz[n0 + 1]);
            oidpos[2 * i]     = ((uint32_t)Bid[n0]     << 16) | (uint32_t)n0;
            oidpos[2 * i + 1] = ((uint32_t)Bid[n0 + 1] << 16) | (uint32_t)(n0 + 1);
            md[2 * i] = 1e10f; md[2 * i + 1] = 1e10f;
            mnx = fminf(mnx, fminf(x0, x1));
            mxx = fmaxf(mxx, fmaxf(x0, x1));
            mny = fminf(mny, fminf(y0, y1));
            mxy = fmaxf(mxy, fmaxf(y0, y1));
        }
        const float xlo = warp_min_f(mnx);   // exact warp bounding box
        const float xhi = warp_max_f(mxx);
        const float ylo = warp_min_f(mny);
        const float yhi = warp_max_f(mxy);

        float cx = X[0], cy = Y[0], cz = Z[0];
        float bvl = 1e10f;
        uint32_t wbits = __float_as_uint(1e10f);
        float    wmaxf = 1e10f;
        uint32_t q32w  = 0xFFFFFFFFu;        // cached warp packet (for skipped iters)
        __syncthreads();

        for (int it = 0; it < NUM_GROUP; it++) {
            const int p = it & 1;
            if (tid == 0) {
                if ((it & 7) == 0 && it > 0) st_release_gpu(&g_prog[b], it);
                cout[it * 3 + 0] = cx;
                cout[it * 3 + 1] = cy;
                cout[it * 3 + 2] = cz;
            }
            if (it == NUM_GROUP - 1) break;

            // exact 2-D box pruning: skip leaves all md (hence packet) bit-unchanged
            float Lx = (cx < xlo) ? (xlo - cx) : ((cx > xhi) ? (cx - xhi) : 0.0f);
            float Ly = (cy < ylo) ? (ylo - cy) : ((cy > yhi) ? (cy - yhi) : 0.0f);
            float bound = Lx * Lx + Ly * Ly;
            bool skip = (bound * 0.9999f) >= wmaxf;    // warp-uniform

            if (!skip) {
                const ull ncx = pack2(-cx, -cx), ncy = pack2(-cy, -cy), ncz = pack2(-cz, -cz);
                float bm0 = -2.0f, bm1 = -2.0f;
                #pragma unroll
                for (int i = 0; i < 8; i++) {
                    ull dx = addx2(pxp[i], ncx);
                    ull dy = addx2(pyp[i], ncy);
                    ull dz = addx2(pzp[i], ncz);
                    ull m  = mulx2(dx, dx);
                    m = fma2_(dy, dy, m);
                    m = fma2_(dz, dz, m);    // == fmaf(dz,dz,fmaf(dy,dy,dx*dx)) per lane
                    float d0, d1; unpack2(m, d0, d1);
                    float m0 = fminf(md[2 * i],     d0);
                    float m1 = fminf(md[2 * i + 1], d1);
                    md[2 * i]     = m0;
                    md[2 * i + 1] = m1;
                    bm0 = fmaxf(bm0, m0);
                    bm1 = fmaxf(bm1, m1);
                }
                bvl = fmaxf(bm0, bm1);
                uint32_t fb = (bvl >= 0.0f) ? __float_as_uint(bvl) : 0u;
                wbits = redux_max_u32(fb);           // md>=0 -> bits monotone
                wmaxf = __uint_as_float(wbits);

                // pre-resolve warp's full answer: min (oid<<16|pos) among value hits
                uint32_t q = 0xFFFFFFFFu;
                #pragma unroll
                for (int j = 0; j < 16; j++)
                    q = (md[j] == wmaxf && oidpos[j] < q) ? oidpos[j] : q;
                q32w = redux_min_u32(q);             // warp min-oid packet (uniform)
            }
            if (lane == 0) {
                vbuf[p][warp] = wbits;
                pbuf[p][warp] = q32w;
            }
            __syncthreads();                          // the ONLY barrier

            // every warp redundantly reduces the 16-entry table
            uint32_t v2 = vbuf[p][lane];
            uint32_t p2 = pbuf[p][lane];
            uint32_t m2 = redux_max_u32(v2);          // block max value
            uint32_t sel = (v2 == m2) ? p2 : 0xFFFFFFFFu;
            uint32_t pm  = redux_min_u32(sel);        // min oid among ties (exact)
            int pos = (int)(pm & 0xFFFFu);

            cx = Bx[pos]; cy = By[pos]; cz = Bz[pos]; // parallel broadcast LDS
        }
        if (tid == 0) st_release_gpu(&g_prog[b], NUM_GROUP);
    } else {
        // ==================== kNN top-32 (r10 streaming, batch-major) ====================
        float* sx = s;
        float* sy = s + N;
        float* sz = s + 2 * N;

        const int kb    = blockIdx.x - B;
        const int b     = kb % B;
        const int chunk = kb / B;
        const int g     = chunk * 16 + warp;

        const float* X = xyz + (size_t)b * 3 * N;
        const float4* X4 = (const float4*)X;
        float4* sx4 = (float4*)sx;
        float4* sy4 = (float4*)sy;
        float4* sz4 = (float4*)sz;
        const int N4 = N >> 2;
        for (int n = tid; n < N4; n += TPB) {
            sx4[n] = X4[n];
            sy4[n] = X4[N4 + n];
            sz4[n] = X4[2 * N4 + n];
        }
        __syncthreads();

        if (lane == 0) {
            while (ld_acquire_gpu(&g_prog[b]) < g + 1) __nanosleep(512);
        }
        __syncwarp();

        const float* c = centers + ((size_t)b * NUM_GROUP + g) * 3;
        const float cx = __ldcg(&c[0]), cy = __ldcg(&c[1]), cz = __ldcg(&c[2]);

        // init with first 32 points, bitonic sort ascending u64 keys
        ull key;
        {
            float dx = sx[lane] - cx, dy = sy[lane] - cy, dz = sz[lane] - cz;
            float d2 = fmaf(dz, dz, fmaf(dy, dy, dx * dx));
            key = ((ull)__float_as_uint(d2) << 32) | (uint32_t)lane;
        }
        #pragma unroll
        for (int k2 = 2; k2 <= 32; k2 <<= 1) {
            #pragma unroll
            for (int j = k2 >> 1; j > 0; j >>= 1) {
                ull partner = __shfl_xor_sync(FULL, key, j);
                bool lower  = (lane & j) == 0;
                bool asc    = (lane & k2) == 0;
                ull mn = (key < partner) ? key : partner;
                ull mx = (key < partner) ? partner : key;
                key = (lower == asc) ? mn : mx;
            }
        }
        ull kmax = __shfl_sync(FULL, key, 31);

        // scalar step for points [32, 64)
        {
            int idx = 32 + lane;
            float dx = sx[idx] - cx, dy = sy[idx] - cy, dz = sz[idx] - cz;
            float d2 = fmaf(dz, dz, fmaf(dy, dy, dx * dx));
            ull nk = ((ull)__float_as_uint(d2) << 32) | (uint32_t)idx;
            unsigned mask = __ballot_sync(FULL, nk < kmax);
            while (mask) {
                int src = __ffs(mask) - 1;
                mask &= mask - 1;
                ull cand = __shfl_sync(FULL, nk, src);
                if (cand >= kmax) continue;
                int pos = __popc(__ballot_sync(FULL, key < cand));
                ull up  = __shfl_up_sync(FULL, key, 1);
                if (lane == pos)      key = cand;
                else if (lane > pos)  key = up;
                kmax = __shfl_sync(FULL, key, 31);
            }
        }

        // packed stream: 64 candidates per step
        const float2* sx2 = (const float2*)sx;
        const float2* sy2 = (const float2*)sy;
        const float2* sz2 = (const float2*)sz;
        const ull ncx = pack2(-cx, -cx), ncy = pack2(-cy, -cy), ncz = pack2(-cz, -cz);

        for (int base2 = 64; base2 < N; base2 += 64) {
            int h = (base2 >> 1) + lane;
            float2 xx = sx2[h], yy = sy2[h], zz = sz2[h];
            ull dx = addx2(pack2(xx.x, xx.y), ncx);
            ull dy = addx2(pack2(yy.x, yy.y), ncy);
            ull dz = addx2(pack2(zz.x, zz.y), ncz);
            ull m  = mulx2(dx, dx);
            m = fma2_(dy, dy, m);
            m = fma2_(dz, dz, m);
            float d0, d1; unpack2(m, d0, d1);
            int i0 = base2 + 2 * lane;
            ull k0 = ((ull)__float_as_uint(d0) << 32) | (uint32_t)i0;
            ull k1 = ((ull)__float_as_uint(d1) << 32) | (uint32_t)(i0 + 1);

            unsigned m0 = __ballot_sync(FULL, k0 < kmax);
            unsigned m1 = __ballot_sync(FULL, k1 < kmax);
            while (m0) {
                int src = __ffs(m0) - 1;
                m0 &= m0 - 1;
                ull cand = __shfl_sync(FULL, k0, src);
                if (cand >= kmax) continue;
                int pos = __popc(__ballot_sync(FULL, key < cand));
                ull up  = __shfl_up_sync(FULL, key, 1);
                if (lane == pos)      key = cand;
                else if (lane > pos)  key = up;
                kmax = __shfl_sync(FULL, key, 31);
            }
            while (m1) {
                int src = __ffs(m1) - 1;
                m1 &= m1 - 1;
                ull cand = __shfl_sync(FULL, k1, src);
                if (cand >= kmax) continue;
                int pos = __popc(__ballot_sync(FULL, key < cand));
                ull up  = __shfl_up_sync(FULL, key, 1);
                if (lane == pos)      key = cand;
                else if (lane > pos)  key = up;
                kmax = __shfl_sync(FULL, key, 31);
            }
        }

        // emit: neighborhood = point - center (lane-sorted ascending = top_k order)
        int idx = (int)(uint32_t)key;
        float ox = sx[idx] - cx, oy = sy[idx] - cy, oz = sz[idx] - cz;
        size_t o = (((size_t)b * NUM_GROUP + g) * GROUP_SIZE + lane) * 3;
        nb[o + 0] = ox;
        nb[o + 1] = oy;
        nb[o + 2] = oz;
    }
}

// ============================================================
extern "C" void kernel_launch(void* const* d_in, const int* in_sizes, int n_in,
                              void* d_out, int out_size) {
    const float* xyz = (const float*)d_in[0];
    float* out = (float*)d_out;

    const int B = out_size / (NUM_GROUP * (GROUP_SIZE + 1) * 3);
    const int N = in_sizes[0] / (3 * B);

    float* nb      = out;
    float* centers = out + (size_t)B * NUM_GROUP * GROUP_SIZE * 3;

    const int knnBlocks = B * (NUM_GROUP / 16);
    size_t smem = (size_t)(4 * N + NBKT) * sizeof(float);   // Bx,By,Bz,Bid + hist
    if (smem < 120 * 1024) smem = 120 * 1024;               // force 1 block/SM

    init_prog<<<1, MAXB>>>();

    cudaFuncSetAttribute(fused_kernel, cudaFuncAttributeMaxDynamicSharedMemorySize, (int)smem);
    fused_kernel<<<B + knnBlocks, TPB, smem>>>(xyz, nb, centers, N, B);
}

// round 17
// speedup vs baseline: 1.0018x; 1.0018x over previous
#include <cuda_runtime.h>
#include <cstdint>

typedef unsigned long long ull;
#define FULL 0xFFFFFFFFu

constexpr int NUM_GROUP  = 512;
constexpr int GROUP_SIZE = 32;
constexpr int TPB        = 512;
constexpr int MAXB       = 64;
constexpr int NBKT       = 4096;

__device__ int g_prog[MAXB];

__global__ void init_prog() {
    if (threadIdx.x < MAXB) g_prog[threadIdx.x] = 0;
}

// ---- packed f32x2 helpers (sm_100+) ----
__device__ __forceinline__ ull pack2(float a, float b) {
    ull r; asm("mov.b64 %0,{%1,%2};" : "=l"(r) : "f"(a), "f"(b)); return r;
}
__device__ __forceinline__ void unpack2(ull v, float& a, float& b) {
    asm("mov.b64 {%0,%1},%2;" : "=f"(a), "=f"(b) : "l"(v));
}
__device__ __forceinline__ ull addx2(ull a, ull b) {
    ull r; asm("add.rn.f32x2 %0,%1,%2;" : "=l"(r) : "l"(a), "l"(b)); return r;
}
__device__ __forceinline__ ull mulx2(ull a, ull b) {
    ull r; asm("mul.rn.f32x2 %0,%1,%2;" : "=l"(r) : "l"(a), "l"(b)); return r;
}
__device__ __forceinline__ ull fma2_(ull a, ull b, ull c) {
    ull r; asm("fma.rn.f32x2 %0,%1,%2,%3;" : "=l"(r) : "l"(a), "l"(b), "l"(c)); return r;
}
__device__ __forceinline__ uint32_t redux_max_u32(uint32_t v) {
    uint32_t r; asm("redux.sync.max.u32 %0, %1, 0xffffffff;" : "=r"(r) : "r"(v)); return r;
}
__device__ __forceinline__ uint32_t redux_min_u32(uint32_t v) {
    uint32_t r; asm("redux.sync.min.u32 %0, %1, 0xffffffff;" : "=r"(r) : "r"(v)); return r;
}
__device__ __forceinline__ void st_release_gpu(int* p, int v) {
    asm volatile("st.release.gpu.global.s32 [%0], %1;" :: "l"(p), "r"(v) : "memory");
}
__device__ __forceinline__ int ld_acquire_gpu(const int* p) {
    int v; asm volatile("ld.acquire.gpu.global.s32 %0, [%1];" : "=r"(v) : "l"(p) : "memory");
    return v;
}
__device__ __forceinline__ float warp_min_f(float v) {
    #pragma unroll
    for (int o = 16; o > 0; o >>= 1) v = fminf(v, __shfl_xor_sync(FULL, v, o));
    return v;
}
__device__ __forceinline__ float warp_max_f(float v) {
    #pragma unroll
    for (int o = 16; o > 0; o >>= 1) v = fmaxf(v, __shfl_xor_sync(FULL, v, o));
    return v;
}

// ============================================================
// Fused kernel, TPB=512:
//   blocks [0, B)        : FPS — single barrier/iter, x-sorted slabs, 1-D prune
//   blocks [B, B + 32*B) : kNN (r10 streaming, proven), batch-major
// FPS smem: Bx[N] By[N] Bz[N] floats, Bid[N] int, hist[NBKT] int
// ============================================================
__global__ __launch_bounds__(TPB)
void fused_kernel(const float* __restrict__ xyz,
                  float* __restrict__ nb,
                  float* __restrict__ centers,
                  int N, int B) {
    extern __shared__ float s[];
    const int tid  = threadIdx.x;
    const int lane = tid & 31;
    const int warp = tid >> 5;

    __shared__ int partial[TPB];

    if (blockIdx.x < (unsigned)B) {
        // ==================== FPS ====================
        const int b = blockIdx.x;
        const float* X = xyz + (size_t)b * 3 * N;
        const float* Y = X + N;
        const float* Z = Y + N;
        float* cout = centers + (size_t)b * NUM_GROUP * 3;

        float* Bx = s;
        float* By = s + N;
        float* Bz = s + 2 * N;
        int*   Bid  = (int*)(s + 3 * N);
        int*   hist = (int*)(s + 4 * N);

        __shared__ uint32_t vbuf[2][32];   // per-warp value bits (lanes 16..31 stay 0)
        __shared__ uint32_t pbuf[2][32];   // per-warp packed (oid<<16 | pos)
        if (tid < 64) {
            vbuf[tid >> 5][tid & 31] = 0u;
            pbuf[tid >> 5][tid & 31] = 0xFFFFFFFFu;
        }

        // ---- counting sort by x (4096 buckets over [-5,5]) ----
        #pragma unroll
        for (int k = 0; k < NBKT / TPB; k++) hist[tid + k * TPB] = 0;
        __syncthreads();
        for (int i = tid; i < N; i += TPB) {
            float x = X[i];
            int bkt = (int)((x + 5.0f) * 409.6f);
            bkt = max(0, min(NBKT - 1, bkt));
            atomicAdd(&hist[bkt], 1);
        }
        __syncthreads();
        int loc[8], mysum = 0;
        #pragma unroll
        for (int k = 0; k < 8; k++) { loc[k] = hist[tid * 8 + k]; mysum += loc[k]; }
        partial[tid] = mysum;
        __syncthreads();
        for (int off = 1; off < TPB; off <<= 1) {
            int v = (tid >= off) ? partial[tid - off] : 0;
            __syncthreads();
            partial[tid] += v;
            __syncthreads();
        }
        {
            int run = partial[tid] - mysum;
            #pragma unroll
            for (int k = 0; k < 8; k++) { int c = loc[k]; hist[tid * 8 + k] = run; run += c; }
        }
        __syncthreads();
        for (int i = tid; i < N; i += TPB) {
            float x = X[i];
            int bkt = (int)((x + 5.0f) * 409.6f);
            bkt = max(0, min(NBKT - 1, bkt));
            int pos = atomicAdd(&hist[bkt], 1);
            Bx[pos]  = x;
            By[pos]  = Y[i];
            Bz[pos]  = Z[i];
            Bid[pos] = i;
        }
        __syncthreads();

        // ---- 16 contiguous sorted points per thread ----
        ull  pxp[8], pyp[8], pzp[8];
        uint32_t oidpos[16];               // (original_id << 16) | sorted_pos
        float md[16];
        const int base = 512 * warp + 16 * lane;
        float mnx = 1e30f, mxx = -1e30f;
        #pragma unroll
        for (int i = 0; i < 8; i++) {
            int n0 = base + 2 * i;
            float x0 = Bx[n0], x1 = Bx[n0 + 1];
            pxp[i] = pack2(x0, x1);
            pyp[i] = pack2(By[n0], By[n0 + 1]);
            pzp[i] = pack2(Bz[n0], Bz[n0 + 1]);
            oidpos[2 * i]     = ((uint32_t)Bid[n0]     << 16) | (uint32_t)n0;
            oidpos[2 * i + 1] = ((uint32_t)Bid[n0 + 1] << 16) | (uint32_t)(n0 + 1);
            md[2 * i] = 1e10f; md[2 * i + 1] = 1e10f;
            mnx = fminf(mnx, fminf(x0, x1));
            mxx = fmaxf(mxx, fmaxf(x0, x1));
        }
        const float xlo = warp_min_f(mnx);   // exact slab bounds (warp-uniform)
        const float xhi = warp_max_f(mxx);

        float cx = X[0], cy = Y[0], cz = Z[0];
        uint32_t wbits = __float_as_uint(1e10f);
        float    wmaxf = 1e10f;
        uint32_t q32w  = 0xFFFFFFFFu;        // cached warp packet (for skipped iters)
        __syncthreads();

        for (int it = 0; it < NUM_GROUP; it++) {
            const int p = it & 1;
            if (tid == 0) {
                if ((it & 3) == 0 && it > 0) st_release_gpu(&g_prog[b], it);  // lag-4 publish
                cout[it * 3 + 0] = cx;
                cout[it * 3 + 1] = cy;
                cout[it * 3 + 2] = cz;
            }
            if (it == NUM_GROUP - 1) break;

            // exact slab pruning: skip leaves all md (hence packet) bit-unchanged
            float L = (cx < xlo) ? (xlo - cx) : ((cx > xhi) ? (cx - xhi) : 0.0f);
            bool skip = (L * L * 0.99999f) >= wmaxf;   // warp-uniform

            if (!skip) {
                const ull ncx = pack2(-cx, -cx), ncy = pack2(-cy, -cy), ncz = pack2(-cz, -cz);
                float bm0 = -2.0f, bm1 = -2.0f;
                #pragma unroll
                for (int i = 0; i < 8; i++) {
                    ull dx = addx2(pxp[i], ncx);
                    ull dy = addx2(pyp[i], ncy);
                    ull dz = addx2(pzp[i], ncz);
                    ull m  = mulx2(dx, dx);
                    m = fma2_(dy, dy, m);
                    m = fma2_(dz, dz, m);    // == fmaf(dz,dz,fmaf(dy,dy,dx*dx)) per lane
                    float d0, d1; unpack2(m, d0, d1);
                    float m0 = fminf(md[2 * i],     d0);
                    float m1 = fminf(md[2 * i + 1], d1);
                    md[2 * i]     = m0;
                    md[2 * i + 1] = m1;
                    bm0 = fmaxf(bm0, m0);
                    bm1 = fmaxf(bm1, m1);
                }
                float bvl = fmaxf(bm0, bm1);
                uint32_t fb = (bvl >= 0.0f) ? __float_as_uint(bvl) : 0u;
                wbits = redux_max_u32(fb);           // md>=0 -> bits monotone
                wmaxf = __uint_as_float(wbits);

                // pre-resolve warp packet: min (oid<<16|pos) among value hits,
                // via 16 independent SELs + 4-level static min tree (short latency)
                uint32_t t[16];
                #pragma unroll
                for (int j = 0; j < 16; j++)
                    t[j] = (md[j] == wmaxf) ? oidpos[j] : 0xFFFFFFFFu;
                #pragma unroll
                for (int st = 8; st > 0; st >>= 1) {
                    #pragma unroll
                    for (int k = 0; k < 8; k++)
                        if (k < st) t[k] = min(t[k], t[k + st]);
                }
                q32w = redux_min_u32(t[0]);          // warp min-oid packet (uniform)
            }
            if (lane == 0) {
                vbuf[p][warp] = wbits;
                pbuf[p][warp] = q32w;
            }
            __syncthreads();                          // the ONLY barrier

            // every warp redundantly reduces the 16-entry table
            uint32_t v2 = vbuf[p][lane];
            uint32_t p2 = pbuf[p][lane];
            uint32_t m2 = redux_max_u32(v2);          // block max value
            uint32_t sel = (v2 == m2) ? p2 : 0xFFFFFFFFu;
            uint32_t pm  = redux_min_u32(sel);        // min oid among ties (exact)
            int pos = (int)(pm & 0xFFFFu);

            cx = Bx[pos]; cy = By[pos]; cz = Bz[pos]; // parallel broadcast LDS
        }
        if (tid == 0) st_release_gpu(&g_prog[b], NUM_GROUP);
    } else {
        // ==================== kNN top-32 (r10 streaming, batch-major) ====================
        float* sx = s;
        float* sy = s + N;
        float* sz = s + 2 * N;

        const int kb    = blockIdx.x - B;
        const int b     = kb % B;
        const int chunk = kb / B;
        const int g     = chunk * 16 + warp;

        const float* X = xyz + (size_t)b * 3 * N;
        const float4* X4 = (const float4*)X;
        float4* sx4 = (float4*)sx;
        float4* sy4 = (float4*)sy;
        float4* sz4 = (float4*)sz;
        const int N4 = N >> 2;
        for (int n = tid; n < N4; n += TPB) {
            sx4[n] = X4[n];
            sy4[n] = X4[N4 + n];
            sz4[n] = X4[2 * N4 + n];
        }
        __syncthreads();

        if (lane == 0) {
            while (ld_acquire_gpu(&g_prog[b]) < g + 1) __nanosleep(512);
        }
        __syncwarp();

        const float* c = centers + ((size_t)b * NUM_GROUP + g) * 3;
        const float cx = __ldcg(&c[0]), cy = __ldcg(&c[1]), cz = __ldcg(&c[2]);

        // init with first 32 points, bitonic sort ascending u64 keys
        ull key;
        {
            float dx = sx[lane] - cx, dy = sy[lane] - cy, dz = sz[lane] - cz;
            float d2 = fmaf(dz, dz, fmaf(dy, dy, dx * dx));
            key = ((ull)__float_as_uint(d2) << 32) | (uint32_t)lane;
        }
        #pragma unroll
        for (int k2 = 2; k2 <= 32; k2 <<= 1) {
            #pragma unroll
            for (int j = k2 >> 1; j > 0; j >>= 1) {
                ull partner = __shfl_xor_sync(FULL, key, j);
                bool lower  = (lane & j) == 0;
                bool asc    = (lane & k2) == 0;
                ull mn = (key < partner) ? key : partner;
                ull mx = (key < partner) ? partner : key;
                key = (lower == asc) ? mn : mx;
            }
        }
        ull kmax = __shfl_sync(FULL, key, 31);

        // scalar step for points [32, 64)
        {
            int idx = 32 + lane;
            float dx = sx[idx] - cx, dy = sy[idx] - cy, dz = sz[idx] - cz;
            float d2 = fmaf(dz, dz, fmaf(dy, dy, dx * dx));
            ull nk = ((ull)__float_as_uint(d2) << 32) | (uint32_t)idx;
            unsigned mask = __ballot_sync(FULL, nk < kmax);
            while (mask) {
                int src = __ffs(mask) - 1;
                mask &= mask - 1;
                ull cand = __shfl_sync(FULL, nk, src);
                if (cand >= kmax) continue;
                int pos = __popc(__ballot_sync(FULL, key < cand));
                ull up  = __shfl_up_sync(FULL, key, 1);
                if (lane == pos)      key = cand;
                else if (lane > pos)  key = up;
                kmax = __shfl_sync(FULL, key, 31);
            }
        }

        // packed stream: 64 candidates per step
        const float2* sx2 = (const float2*)sx;
        const float2* sy2 = (const float2*)sy;
        const float2* sz2 = (const float2*)sz;
        const ull ncx = pack2(-cx, -cx), ncy = pack2(-cy, -cy), ncz = pack2(-cz, -cz);

        for (int base2 = 64; base2 < N; base2 += 64) {
            int h = (base2 >> 1) + lane;
            float2 xx = sx2[h], yy = sy2[h], zz = sz2[h];
            ull dx = addx2(pack2(xx.x, xx.y), ncx);
            ull dy = addx2(pack2(yy.x, yy.y), ncy);
            ull dz = addx2(pack2(zz.x, zz.y), ncz);
            ull m  = mulx2(dx, dx);
            m = fma2_(dy, dy, m);
            m = fma2_(dz, dz, m);
            float d0, d1; unpack2(m, d0, d1);
            int i0 = base2 + 2 * lane;
            ull k0 = ((ull)__float_as_uint(d0) << 32) | (uint32_t)i0;
            ull k1 = ((ull)__float_as_uint(d1) << 32) | (uint32_t)(i0 + 1);

            unsigned m0 = __ballot_sync(FULL, k0 < kmax);
            unsigned m1 = __ballot_sync(FULL, k1 < kmax);
            while (m0) {
                int src = __ffs(m0) - 1;
                m0 &= m0 - 1;
                ull cand = __shfl_sync(FULL, k0, src);
                if (cand >= kmax) continue;
                int pos = __popc(__ballot_sync(FULL, key < cand));
                ull up  = __shfl_up_sync(FULL, key, 1);
                if (lane == pos)      key = cand;
                else if (lane > pos)  key = up;
                kmax = __shfl_sync(FULL, key, 31);
            }
            while (m1) {
                int src = __ffs(m1) - 1;
                m1 &= m1 - 1;
                ull cand = __shfl_sync(FULL, k1, src);
                if (cand >= kmax) continue;
                int pos = __popc(__ballot_sync(FULL, key < cand));
                ull up  = __shfl_up_sync(FULL, key, 1);
                if (lane == pos)      key = cand;
                else if (lane > pos)  key = up;
                kmax = __shfl_sync(FULL, key, 31);
            }
        }

        // emit: neighborhood = point - center (lane-sorted ascending = top_k order)
        int idx = (int)(uint32_t)key;
        float ox = sx[idx] - cx, oy = sy[idx] - cy, oz = sz[idx] - cz;
        size_t o = (((size_t)b * NUM_GROUP + g) * GROUP_SIZE + lane) * 3;
        nb[o + 0] = ox;
        nb[o + 1] = oy;
        nb[o + 2] = oz;
    }
}

// ============================================================
extern "C" void kernel_launch(void* const* d_in, const int* in_sizes, int n_in,
                              void* d_out, int out_size) {
    const float* xyz = (const float*)d_in[0];
    float* out = (float*)d_out;

    const int B = out_size / (NUM_GROUP * (GROUP_SIZE + 1) * 3);
    const int N = in_sizes[0] / (3 * B);

    float* nb      = out;
    float* centers = out + (size_t)B * NUM_GROUP * GROUP_SIZE * 3;

    const int knnBlocks = B * (NUM_GROUP / 16);
    size_t smem = (size_t)(4 * N + NBKT) * sizeof(float);   // Bx,By,Bz,Bid + hist
    if (smem < 120 * 1024) smem = 120 * 1024;               // force 1 block/SM

    init_prog<<<1, MAXB>>>();

    cudaFuncSetAttribute(fused_kernel, cudaFuncAttributeMaxDynamicSharedMemorySize, (int)smem);
    fused_kernel<<<B + knnBlocks, TPB, smem>>>(xyz, nb, centers, N, B);
}